// round 1
// baseline (speedup 1.0000x reference)
#include <cuda_runtime.h>
#include <cuda_bf16.h>

#define B_   128
#define N_   512
#define FIN  128
#define FOUT 64

// Scratch (allocation-free rule: __device__ globals)
__device__ float g_h[B_ * N_ * FOUT];   // 16.8 MB
__device__ float g_s[B_ * N_];
__device__ float g_t[B_ * N_];

// ---------------------------------------------------------------------------
// Kernel A: h = X @ W   (M=65536, K=128, N=64), 64-row tiles, 256 threads
// ---------------------------------------------------------------------------
__global__ void __launch_bounds__(256) gemm1_kernel(
    const float* __restrict__ X, const float* __restrict__ W)
{
    extern __shared__ float sm[];
    float* Xs = sm;               // [64][132]  (pad 128->132 to kill bank conflicts)
    float* Ws = sm + 64 * 132;    // [128][64]

    const int tid = threadIdx.x;
    const int m0  = blockIdx.x * 64;

    // Load X tile 64x128 (float4, coalesced)
#pragma unroll
    for (int p = 0; p < 8; p++) {
        int u  = p * 256 + tid;
        int r  = u >> 5;
        int k4 = (u & 31) * 4;
        float4 v = *(const float4*)(X + (size_t)(m0 + r) * FIN + k4);
        *(float4*)(Xs + r * 132 + k4) = v;
    }
    // Load W 128x64 (float4, coalesced)
#pragma unroll
    for (int p = 0; p < 8; p++) {
        int u  = p * 256 + tid;
        int k  = u >> 4;
        int c4 = (u & 15) * 4;
        *(float4*)(Ws + k * 64 + c4) = *(const float4*)(W + k * 64 + c4);
    }
    __syncthreads();

    const int tx = tid & 15;   // cols: tx*4 .. tx*4+3
    const int ty = tid >> 4;   // rows: ty*4 .. ty*4+3
    float acc[4][4] = {};

#pragma unroll 8
    for (int k = 0; k < FIN; k++) {
        float4 wv = *(const float4*)(Ws + k * 64 + tx * 4);
        float x0 = Xs[(ty * 4 + 0) * 132 + k];
        float x1 = Xs[(ty * 4 + 1) * 132 + k];
        float x2 = Xs[(ty * 4 + 2) * 132 + k];
        float x3 = Xs[(ty * 4 + 3) * 132 + k];
        acc[0][0] += x0 * wv.x; acc[0][1] += x0 * wv.y; acc[0][2] += x0 * wv.z; acc[0][3] += x0 * wv.w;
        acc[1][0] += x1 * wv.x; acc[1][1] += x1 * wv.y; acc[1][2] += x1 * wv.z; acc[1][3] += x1 * wv.w;
        acc[2][0] += x2 * wv.x; acc[2][1] += x2 * wv.y; acc[2][2] += x2 * wv.z; acc[2][3] += x2 * wv.w;
        acc[3][0] += x3 * wv.x; acc[3][1] += x3 * wv.y; acc[3][2] += x3 * wv.z; acc[3][3] += x3 * wv.w;
    }

#pragma unroll
    for (int i = 0; i < 4; i++) {
        size_t row = (size_t)(m0 + ty * 4 + i);
        float4 o = make_float4(acc[i][0], acc[i][1], acc[i][2], acc[i][3]);
        *(float4*)(g_h + row * FOUT + tx * 4) = o;
    }
}

// ---------------------------------------------------------------------------
// Kernel St: s = h . a_src ; t = h . a_dst   (one warp per row)
// ---------------------------------------------------------------------------
__global__ void __launch_bounds__(256) st_kernel(const float* __restrict__ a)
{
    const int warp = threadIdx.x >> 5;
    const int lane = threadIdx.x & 31;
    const int row  = blockIdx.x * 8 + warp;

    float2 hv = *(const float2*)(g_h + (size_t)row * FOUT + lane * 2);
    float as0 = a[lane * 2],      as1 = a[lane * 2 + 1];
    float ad0 = a[64 + lane * 2], ad1 = a[64 + lane * 2 + 1];

    float s = hv.x * as0 + hv.y * as1;
    float t = hv.x * ad0 + hv.y * ad1;
#pragma unroll
    for (int o = 16; o; o >>= 1) {
        s += __shfl_xor_sync(0xffffffffu, s, o);
        t += __shfl_xor_sync(0xffffffffu, t, o);
    }
    if (lane == 0) { g_s[row] = s; g_t[row] = t; }
}

// ---------------------------------------------------------------------------
// Kernel B: fused masked-softmax + att @ h + leaky_relu(0.01)
// Block = (batch b, 32-row tile). One pass over adj. 256 threads.
// smem: t[512] | att[32][516] | hs[64][64] | inv[32]
// ---------------------------------------------------------------------------
__global__ void __launch_bounds__(256) attn_kernel(
    const int* __restrict__ adj, float* __restrict__ out)
{
    extern __shared__ float sm[];
    float* t_sh = sm;                     // 512
    float* att  = sm + 512;               // 32 * 516 (padded stride)
    float* hs   = att + 32 * 516;         // 64 * 64
    float* inv  = hs + 64 * 64;           // 32

    const int b   = blockIdx.y;
    const int r0  = blockIdx.x * 32;
    const int tid = threadIdx.x;

    t_sh[tid]       = g_t[b * N_ + tid];
    t_sh[tid + 256] = g_t[b * N_ + tid + 256];
    __syncthreads();

    const int warp = tid >> 5;
    const int lane = tid & 31;

    // ---- Phase 1: masked leaky-relu logits + softmax weights (unnormalized) ----
#pragma unroll
    for (int rr = 0; rr < 4; rr++) {
        int r    = warp * 4 + rr;          // local row 0..31
        int grow = r0 + r;
        float s  = g_s[b * N_ + grow];
        const int* arow = adj + ((size_t)b * N_ + grow) * N_;

        float ev[16];
        float mx = -3.4e38f;
#pragma unroll
        for (int jj = 0; jj < 16; jj++) {
            int j   = jj * 32 + lane;
            float e = s + t_sh[j];
            e = e > 0.f ? e : 0.2f * e;              // leaky_relu(alpha=0.2)
            if (arow[j] <= 0) e = -9e15f;            // mask
            ev[jj] = e;
            mx = fmaxf(mx, e);
        }
#pragma unroll
        for (int o = 16; o; o >>= 1) mx = fmaxf(mx, __shfl_xor_sync(0xffffffffu, mx, o));

        float sum = 0.f;
#pragma unroll
        for (int jj = 0; jj < 16; jj++) {
            float w = __expf(ev[jj] - mx);
            att[r * 516 + jj * 32 + lane] = w;
            sum += w;
        }
#pragma unroll
        for (int o = 16; o; o >>= 1) sum += __shfl_xor_sync(0xffffffffu, sum, o);
        if (lane == 0) inv[r] = 1.0f / sum;
    }
    __syncthreads();

    // ---- Phase 2: C[32,64] = att[32,512] @ h[b][512,64] ----
    const int tx = tid & 15;    // cols tx*4..+3
    const int ty = tid >> 4;    // rows ty*2, ty*2+1
    float acc[2][4] = {};
    const float* hb = g_h + (size_t)b * N_ * FOUT;

    for (int k0 = 0; k0 < N_; k0 += 64) {
#pragma unroll
        for (int p = 0; p < 4; p++) {
            int u  = p * 256 + tid;
            int kk = u >> 4;
            int f4 = (u & 15) * 4;
            *(float4*)(hs + kk * 64 + f4) =
                *(const float4*)(hb + (size_t)(k0 + kk) * FOUT + f4);
        }
        __syncthreads();

#pragma unroll
        for (int kk = 0; kk < 64; kk += 4) {
            float a0v[4], a1v[4];
            *(float4*)a0v = *(const float4*)(att + (ty * 2 + 0) * 516 + k0 + kk);
            *(float4*)a1v = *(const float4*)(att + (ty * 2 + 1) * 516 + k0 + kk);
#pragma unroll
            for (int u = 0; u < 4; u++) {
                float4 hv = *(const float4*)(hs + (kk + u) * 64 + tx * 4);
                acc[0][0] += a0v[u] * hv.x; acc[0][1] += a0v[u] * hv.y;
                acc[0][2] += a0v[u] * hv.z; acc[0][3] += a0v[u] * hv.w;
                acc[1][0] += a1v[u] * hv.x; acc[1][1] += a1v[u] * hv.y;
                acc[1][2] += a1v[u] * hv.z; acc[1][3] += a1v[u] * hv.w;
            }
        }
        __syncthreads();
    }

    // ---- Epilogue: normalize, leaky_relu(0.01), store ----
    float is0 = inv[ty * 2 + 0];
    float is1 = inv[ty * 2 + 1];
#pragma unroll
    for (int i = 0; i < 2; i++) {
        float isv = (i == 0) ? is0 : is1;
        float4 o;
        float v0 = acc[i][0] * isv; o.x = v0 > 0.f ? v0 : 0.01f * v0;
        float v1 = acc[i][1] * isv; o.y = v1 > 0.f ? v1 : 0.01f * v1;
        float v2 = acc[i][2] * isv; o.z = v2 > 0.f ? v2 : 0.01f * v2;
        float v3 = acc[i][3] * isv; o.w = v3 > 0.f ? v3 : 0.01f * v3;
        size_t row = (size_t)b * N_ + r0 + ty * 2 + i;
        *(float4*)(out + row * FOUT + tx * 4) = o;
    }
}

// ---------------------------------------------------------------------------
extern "C" void kernel_launch(void* const* d_in, const int* in_sizes, int n_in,
                              void* d_out, int out_size)
{
    const float* X   = (const float*)d_in[0];   // [B,N,FIN]
    const int*   adj = (const int*)  d_in[1];   // [B,N,N]
    const float* W   = (const float*)d_in[2];   // [FIN,FOUT]
    const float* a   = (const float*)d_in[3];   // [2*FOUT,1]
    float* out = (float*)d_out;

    size_t smA = (size_t)(64 * 132 + 128 * 64) * sizeof(float);   // ~65 KB
    cudaFuncSetAttribute(gemm1_kernel, cudaFuncAttributeMaxDynamicSharedMemorySize, (int)smA);
    gemm1_kernel<<<(B_ * N_) / 64, 256, smA>>>(X, W);

    st_kernel<<<(B_ * N_) / 8, 256>>>(a);

    size_t smB = (size_t)(512 + 32 * 516 + 64 * 64 + 32) * sizeof(float);  // ~84.6 KB
    cudaFuncSetAttribute(attn_kernel, cudaFuncAttributeMaxDynamicSharedMemorySize, (int)smB);
    attn_kernel<<<dim3(N_ / 32, B_), 256, smB>>>(adj, out);
}

// round 2
// speedup vs baseline: 1.6581x; 1.6581x over previous
#include <cuda_runtime.h>
#include <cuda_bf16.h>
#include <cstdint>

#define B_   128
#define N_   512
#define FIN  128
#define FOUT 64

// Scratch (allocation-free rule: __device__ globals)
__device__ float         g_h [B_ * N_ * FOUT];   // 16.8 MB fp32 (for s/t)
__device__ __nv_bfloat16 g_hh[B_ * N_ * FOUT];   // hi part, row-major [row][f]
__device__ __nv_bfloat16 g_hl[B_ * N_ * FOUT];   // lo part
__device__ float g_s[B_ * N_];
__device__ float g_t[B_ * N_];

// ---------------------------------------------------------------------------
// PTX helpers
// ---------------------------------------------------------------------------
__device__ __forceinline__ uint32_t smem_u32(const void* p) {
    return (uint32_t)__cvta_generic_to_shared(p);
}
__device__ __forceinline__ void ldsm_x4(uint32_t& r0, uint32_t& r1, uint32_t& r2, uint32_t& r3, uint32_t addr) {
    asm volatile("ldmatrix.sync.aligned.m8n8.x4.shared.b16 {%0,%1,%2,%3}, [%4];\n"
                 : "=r"(r0), "=r"(r1), "=r"(r2), "=r"(r3) : "r"(addr));
}
__device__ __forceinline__ void ldsm_x2t(uint32_t& r0, uint32_t& r1, uint32_t addr) {
    asm volatile("ldmatrix.sync.aligned.m8n8.x2.trans.shared.b16 {%0,%1}, [%2];\n"
                 : "=r"(r0), "=r"(r1) : "r"(addr));
}
__device__ __forceinline__ void mma16816(float* d, uint32_t a0, uint32_t a1, uint32_t a2, uint32_t a3,
                                         uint32_t b0, uint32_t b1) {
    asm volatile("mma.sync.aligned.m16n8k16.row.col.f32.bf16.bf16.f32 "
                 "{%0,%1,%2,%3},{%4,%5,%6,%7},{%8,%9},{%0,%1,%2,%3};\n"
                 : "+f"(d[0]), "+f"(d[1]), "+f"(d[2]), "+f"(d[3])
                 : "r"(a0), "r"(a1), "r"(a2), "r"(a3), "r"(b0), "r"(b1));
}

// ---------------------------------------------------------------------------
// Kernel A: h = X @ W  (M=65536, K=128, N=64); writes fp32 h + bf16 hi/lo split
// ---------------------------------------------------------------------------
__global__ void __launch_bounds__(256) gemm1_kernel(
    const float* __restrict__ X, const float* __restrict__ W)
{
    extern __shared__ float sm[];
    float* Xs = sm;               // [64][132]
    float* Ws = sm + 64 * 132;    // [128][64]

    const int tid = threadIdx.x;
    const int m0  = blockIdx.x * 64;

#pragma unroll
    for (int p = 0; p < 8; p++) {
        int u  = p * 256 + tid;
        int r  = u >> 5;
        int k4 = (u & 31) * 4;
        *(float4*)(Xs + r * 132 + k4) = *(const float4*)(X + (size_t)(m0 + r) * FIN + k4);
    }
#pragma unroll
    for (int p = 0; p < 8; p++) {
        int u  = p * 256 + tid;
        int k  = u >> 4;
        int c4 = (u & 15) * 4;
        *(float4*)(Ws + k * 64 + c4) = *(const float4*)(W + k * 64 + c4);
    }
    __syncthreads();

    const int tx = tid & 15;
    const int ty = tid >> 4;
    float acc[4][4] = {};

#pragma unroll 8
    for (int k = 0; k < FIN; k++) {
        float4 wv = *(const float4*)(Ws + k * 64 + tx * 4);
        float x0 = Xs[(ty * 4 + 0) * 132 + k];
        float x1 = Xs[(ty * 4 + 1) * 132 + k];
        float x2 = Xs[(ty * 4 + 2) * 132 + k];
        float x3 = Xs[(ty * 4 + 3) * 132 + k];
        acc[0][0] += x0 * wv.x; acc[0][1] += x0 * wv.y; acc[0][2] += x0 * wv.z; acc[0][3] += x0 * wv.w;
        acc[1][0] += x1 * wv.x; acc[1][1] += x1 * wv.y; acc[1][2] += x1 * wv.z; acc[1][3] += x1 * wv.w;
        acc[2][0] += x2 * wv.x; acc[2][1] += x2 * wv.y; acc[2][2] += x2 * wv.z; acc[2][3] += x2 * wv.w;
        acc[3][0] += x3 * wv.x; acc[3][1] += x3 * wv.y; acc[3][2] += x3 * wv.z; acc[3][3] += x3 * wv.w;
    }

#pragma unroll
    for (int i = 0; i < 4; i++) {
        size_t row = (size_t)(m0 + ty * 4 + i);
        *(float4*)(g_h + row * FOUT + tx * 4) =
            make_float4(acc[i][0], acc[i][1], acc[i][2], acc[i][3]);
        // hi/lo bf16 split (row-major, coalesced 8B stores)
        __nv_bfloat16 hi[4], lo[4];
#pragma unroll
        for (int c = 0; c < 4; c++) {
            hi[c] = __float2bfloat16(acc[i][c]);
            lo[c] = __float2bfloat16(acc[i][c] - __bfloat162float(hi[c]));
        }
        *(uint2*)(g_hh + row * FOUT + tx * 4) = *(uint2*)hi;
        *(uint2*)(g_hl + row * FOUT + tx * 4) = *(uint2*)lo;
    }
}

// ---------------------------------------------------------------------------
// Kernel St: s = h . a_src ; t = h . a_dst  (one warp per row)
// ---------------------------------------------------------------------------
__global__ void __launch_bounds__(256) st_kernel(const float* __restrict__ a)
{
    const int warp = threadIdx.x >> 5;
    const int lane = threadIdx.x & 31;
    const int row  = blockIdx.x * 8 + warp;

    float2 hv = *(const float2*)(g_h + (size_t)row * FOUT + lane * 2);
    float s = hv.x * a[lane * 2]      + hv.y * a[lane * 2 + 1];
    float t = hv.x * a[64 + lane * 2] + hv.y * a[64 + lane * 2 + 1];
#pragma unroll
    for (int o = 16; o; o >>= 1) {
        s += __shfl_xor_sync(0xffffffffu, s, o);
        t += __shfl_xor_sync(0xffffffffu, t, o);
    }
    if (lane == 0) { g_s[row] = s; g_t[row] = t; }
}

// ---------------------------------------------------------------------------
// Kernel B: fused masked-softmax + tensor-core att@h (bf16 hi/lo split) + lrelu
// Block = (32-row tile, batch). 256 threads = 8 warps.
// ---------------------------------------------------------------------------
#define ATT_S 520   // bf16 stride for att rows (512 + 8 pad)
#define HS_S  72    // bf16 stride for h chunk rows (64 + 8 pad)

__global__ void __launch_bounds__(256) attn_kernel(
    const int* __restrict__ adj, float* __restrict__ out)
{
    extern __shared__ char smraw[];
    float* t_sh = (float*)smraw;                               // 512 f32
    float* inv  = t_sh + 512;                                  // 32 f32
    __nv_bfloat16* attHi = (__nv_bfloat16*)(inv + 32);         // 32 x 520
    __nv_bfloat16* attLo = attHi + 32 * ATT_S;                 // 32 x 520
    __nv_bfloat16* hsHi  = attLo + 32 * ATT_S;                 // 64 x 72
    __nv_bfloat16* hsLo  = hsHi + 64 * HS_S;                   // 64 x 72

    const int b   = blockIdx.y;
    const int r0  = blockIdx.x * 32;
    const int tid = threadIdx.x;
    const int warp = tid >> 5;
    const int lane = tid & 31;

    t_sh[tid]       = g_t[b * N_ + tid];
    t_sh[tid + 256] = g_t[b * N_ + tid + 256];
    __syncthreads();

    // ---- Phase 1: masked leaky logits -> unnormalized softmax weights (bf16 hi/lo) ----
#pragma unroll
    for (int rr = 0; rr < 4; rr++) {
        int r    = warp * 4 + rr;
        int grow = r0 + r;
        float s  = g_s[b * N_ + grow];
        const int* arow = adj + ((size_t)b * N_ + grow) * N_;

        float ev[16];
        float mx = -3.4e38f;
#pragma unroll
        for (int jj = 0; jj < 16; jj++) {
            int j   = jj * 32 + lane;
            float e = s + t_sh[j];
            e = e > 0.f ? e : 0.2f * e;
            if (arow[j] <= 0) e = -9e15f;
            ev[jj] = e;
            mx = fmaxf(mx, e);
        }
#pragma unroll
        for (int o = 16; o; o >>= 1) mx = fmaxf(mx, __shfl_xor_sync(0xffffffffu, mx, o));

        float sum = 0.f;
#pragma unroll
        for (int jj = 0; jj < 16; jj++) {
            float w = __expf(ev[jj] - mx);
            __nv_bfloat16 hi = __float2bfloat16(w);
            __nv_bfloat16 lo = __float2bfloat16(w - __bfloat162float(hi));
            attHi[r * ATT_S + jj * 32 + lane] = hi;
            attLo[r * ATT_S + jj * 32 + lane] = lo;
            sum += w;
        }
#pragma unroll
        for (int o = 16; o; o >>= 1) sum += __shfl_xor_sync(0xffffffffu, sum, o);
        if (lane == 0) inv[r] = 1.0f / sum;
    }
    __syncthreads();

    // ---- Phase 2: C[32,64] = att @ h[b]  via mma.m16n8k16.bf16 (3-term split) ----
    // warp -> output tiles: mtile = warp>>2 (2 x m16), ntiles {(warp&3)*2, +1} (8 x n8)
    const int mtile = warp >> 2;
    const int ntg0  = (warp & 3) * 2;

    // per-lane ldmatrix addresses
    const int lrow16 = lane & 15;
    // A: lanes 0-15 -> rows m..m+15 @ col k; lanes 16-31 -> rows @ col k+8
    uint32_t aAddrHi = smem_u32(attHi + (mtile * 16 + lrow16) * ATT_S + (lane >> 4) * 8);
    uint32_t aAddrLo = smem_u32(attLo + (mtile * 16 + lrow16) * ATT_S + (lane >> 4) * 8);
    // B: lanes 0-15 -> rows k..k+15 @ col nt*8 (trans)
    uint32_t bAddrHi0 = smem_u32(hsHi + lrow16 * HS_S + (ntg0 + 0) * 8);
    uint32_t bAddrHi1 = smem_u32(hsHi + lrow16 * HS_S + (ntg0 + 1) * 8);
    uint32_t bAddrLo0 = smem_u32(hsLo + lrow16 * HS_S + (ntg0 + 0) * 8);
    uint32_t bAddrLo1 = smem_u32(hsLo + lrow16 * HS_S + (ntg0 + 1) * 8);

    float acc0[4] = {0.f, 0.f, 0.f, 0.f};
    float acc1[4] = {0.f, 0.f, 0.f, 0.f};

    const __nv_bfloat16* hbHi = g_hh + (size_t)b * N_ * FOUT;
    const __nv_bfloat16* hbLo = g_hl + (size_t)b * N_ * FOUT;

    for (int c = 0; c < 8; c++) {
        const int k0 = c * 64;
        // load h chunk [64 k-rows][64 f] hi+lo into smem (uint4 = 8 bf16)
#pragma unroll
        for (int rep = 0; rep < 2; rep++) {
            int u   = rep * 256 + tid;
            int row = u >> 3;
            int off = (u & 7) * 8;
            *(uint4*)(hsHi + row * HS_S + off) = *(const uint4*)(hbHi + (size_t)(k0 + row) * FOUT + off);
            *(uint4*)(hsLo + row * HS_S + off) = *(const uint4*)(hbLo + (size_t)(k0 + row) * FOUT + off);
        }
        __syncthreads();

#pragma unroll
        for (int ks = 0; ks < 4; ks++) {
            const uint32_t aOff = (uint32_t)(k0 + ks * 16) * 2;  // bytes along att row
            const uint32_t bOff = (uint32_t)(ks * 16) * HS_S * 2;

            uint32_t ah[4], al[4];
            ldsm_x4(ah[0], ah[1], ah[2], ah[3], aAddrHi + aOff);
            ldsm_x4(al[0], al[1], al[2], al[3], aAddrLo + aOff);

            uint32_t bh0[2], bl0[2], bh1[2], bl1[2];
            ldsm_x2t(bh0[0], bh0[1], bAddrHi0 + bOff);
            ldsm_x2t(bl0[0], bl0[1], bAddrLo0 + bOff);
            ldsm_x2t(bh1[0], bh1[1], bAddrHi1 + bOff);
            ldsm_x2t(bl1[0], bl1[1], bAddrLo1 + bOff);

            // 3-term split: hi*hi + hi*lo + lo*hi
            mma16816(acc0, ah[0], ah[1], ah[2], ah[3], bh0[0], bh0[1]);
            mma16816(acc0, ah[0], ah[1], ah[2], ah[3], bl0[0], bl0[1]);
            mma16816(acc0, al[0], al[1], al[2], al[3], bh0[0], bh0[1]);

            mma16816(acc1, ah[0], ah[1], ah[2], ah[3], bh1[0], bh1[1]);
            mma16816(acc1, ah[0], ah[1], ah[2], ah[3], bl1[0], bl1[1]);
            mma16816(acc1, al[0], al[1], al[2], al[3], bh1[0], bh1[1]);
        }
        __syncthreads();
    }

    // ---- Epilogue: normalize + leaky_relu(0.01) + store ----
    const int gid = lane >> 2;
    const int tg  = lane & 3;
    const int rA  = mtile * 16 + gid;       // rows for c0,c1
    const int rB  = rA + 8;                 // rows for c2,c3
    const float invA = inv[rA];
    const float invB = inv[rB];

#pragma unroll
    for (int nt = 0; nt < 2; nt++) {
        float* acc = nt ? acc1 : acc0;
        int col = (ntg0 + nt) * 8 + tg * 2;
        float v;
        float2 oA, oB;
        v = acc[0] * invA; oA.x = v > 0.f ? v : 0.01f * v;
        v = acc[1] * invA; oA.y = v > 0.f ? v : 0.01f * v;
        v = acc[2] * invB; oB.x = v > 0.f ? v : 0.01f * v;
        v = acc[3] * invB; oB.y = v > 0.f ? v : 0.01f * v;
        *(float2*)(out + ((size_t)b * N_ + r0 + rA) * FOUT + col) = oA;
        *(float2*)(out + ((size_t)b * N_ + r0 + rB) * FOUT + col) = oB;
    }
}

// ---------------------------------------------------------------------------
extern "C" void kernel_launch(void* const* d_in, const int* in_sizes, int n_in,
                              void* d_out, int out_size)
{
    const float* X   = (const float*)d_in[0];
    const int*   adj = (const int*)  d_in[1];
    const float* W   = (const float*)d_in[2];
    const float* a   = (const float*)d_in[3];
    float* out = (float*)d_out;

    size_t smA = (size_t)(64 * 132 + 128 * 64) * sizeof(float);
    cudaFuncSetAttribute(gemm1_kernel, cudaFuncAttributeMaxDynamicSharedMemorySize, (int)smA);
    gemm1_kernel<<<(B_ * N_) / 64, 256, smA>>>(X, W);

    st_kernel<<<(B_ * N_) / 8, 256>>>(a);

    size_t smB = (512 + 32) * sizeof(float)
               + (size_t)(2 * 32 * ATT_S + 2 * 64 * HS_S) * sizeof(__nv_bfloat16);
    cudaFuncSetAttribute(attn_kernel, cudaFuncAttributeMaxDynamicSharedMemorySize, (int)smB);
    attn_kernel<<<dim3(N_ / 32, B_), 256, smB>>>(adj, out);
}

// round 3
// speedup vs baseline: 2.1492x; 1.2962x over previous
#include <cuda_runtime.h>
#include <cuda_fp16.h>
#include <cstdint>

#define B_   128
#define N_   512
#define FIN  128
#define FOUT 64

// Scratch (allocation-free rule: __device__ globals)
__device__ __half g_hh[B_ * N_ * FOUT];   // h hi part fp16, row-major [row][f]
__device__ __half g_hl[B_ * N_ * FOUT];   // h lo part fp16
__device__ float  g_s[B_ * N_];
__device__ float  g_t[B_ * N_];

// ---------------------------------------------------------------------------
// PTX helpers
// ---------------------------------------------------------------------------
__device__ __forceinline__ uint32_t smem_u32(const void* p) {
    return (uint32_t)__cvta_generic_to_shared(p);
}
__device__ __forceinline__ void ldsm_x4(uint32_t& r0, uint32_t& r1, uint32_t& r2, uint32_t& r3, uint32_t addr) {
    asm volatile("ldmatrix.sync.aligned.m8n8.x4.shared.b16 {%0,%1,%2,%3}, [%4];\n"
                 : "=r"(r0), "=r"(r1), "=r"(r2), "=r"(r3) : "r"(addr));
}
__device__ __forceinline__ void ldsm_x4t(uint32_t& r0, uint32_t& r1, uint32_t& r2, uint32_t& r3, uint32_t addr) {
    asm volatile("ldmatrix.sync.aligned.m8n8.x4.trans.shared.b16 {%0,%1,%2,%3}, [%4];\n"
                 : "=r"(r0), "=r"(r1), "=r"(r2), "=r"(r3) : "r"(addr));
}
__device__ __forceinline__ void mma16816(float* d, uint32_t a0, uint32_t a1, uint32_t a2, uint32_t a3,
                                         uint32_t b0, uint32_t b1) {
    asm volatile("mma.sync.aligned.m16n8k16.row.col.f32.f16.f16.f32 "
                 "{%0,%1,%2,%3},{%4,%5,%6,%7},{%8,%9},{%0,%1,%2,%3};\n"
                 : "+f"(d[0]), "+f"(d[1]), "+f"(d[2]), "+f"(d[3])
                 : "r"(a0), "r"(a1), "r"(a2), "r"(a3), "r"(b0), "r"(b1));
}

// ---------------------------------------------------------------------------
// Kernel A: h = X @ W  (M=65536, K=128, N=64)
//   writes fp16 hi/lo split of h, and fused s = h.a_src, t = h.a_dst
// ---------------------------------------------------------------------------
__global__ void __launch_bounds__(256) gemm1_kernel(
    const float* __restrict__ X, const float* __restrict__ W,
    const float* __restrict__ a)
{
    extern __shared__ float sm[];
    float* Xs = sm;               // [64][132]
    float* Ws = sm + 64 * 132;    // [128][64]

    const int tid = threadIdx.x;
    const int m0  = blockIdx.x * 64;

#pragma unroll
    for (int p = 0; p < 8; p++) {
        int u  = p * 256 + tid;
        int r  = u >> 5;
        int k4 = (u & 31) * 4;
        *(float4*)(Xs + r * 132 + k4) = *(const float4*)(X + (size_t)(m0 + r) * FIN + k4);
    }
#pragma unroll
    for (int p = 0; p < 8; p++) {
        int u  = p * 256 + tid;
        int k  = u >> 4;
        int c4 = (u & 15) * 4;
        *(float4*)(Ws + k * 64 + c4) = *(const float4*)(W + k * 64 + c4);
    }
    __syncthreads();

    const int tx = tid & 15;
    const int ty = tid >> 4;
    float acc[4][4] = {};

#pragma unroll 8
    for (int k = 0; k < FIN; k++) {
        float4 wv = *(const float4*)(Ws + k * 64 + tx * 4);
        float x0 = Xs[(ty * 4 + 0) * 132 + k];
        float x1 = Xs[(ty * 4 + 1) * 132 + k];
        float x2 = Xs[(ty * 4 + 2) * 132 + k];
        float x3 = Xs[(ty * 4 + 3) * 132 + k];
        acc[0][0] += x0 * wv.x; acc[0][1] += x0 * wv.y; acc[0][2] += x0 * wv.z; acc[0][3] += x0 * wv.w;
        acc[1][0] += x1 * wv.x; acc[1][1] += x1 * wv.y; acc[1][2] += x1 * wv.z; acc[1][3] += x1 * wv.w;
        acc[2][0] += x2 * wv.x; acc[2][1] += x2 * wv.y; acc[2][2] += x2 * wv.z; acc[2][3] += x2 * wv.w;
        acc[3][0] += x3 * wv.x; acc[3][1] += x3 * wv.y; acc[3][2] += x3 * wv.z; acc[3][3] += x3 * wv.w;
    }

    // a_src / a_dst slices for this thread's 4 columns
    float as[4], ad[4];
#pragma unroll
    for (int c = 0; c < 4; c++) {
        as[c] = __ldg(a + tx * 4 + c);
        ad[c] = __ldg(a + 64 + tx * 4 + c);
    }

#pragma unroll
    for (int i = 0; i < 4; i++) {
        size_t row = (size_t)(m0 + ty * 4 + i);
        // fp16 hi/lo split of h (coalesced 8B stores)
        __half hi[4], lo[4];
#pragma unroll
        for (int c = 0; c < 4; c++) {
            hi[c] = __float2half(acc[i][c]);
            lo[c] = __float2half(acc[i][c] - __half2float(hi[c]));
        }
        *(uint2*)(g_hh + row * FOUT + tx * 4) = *(uint2*)hi;
        *(uint2*)(g_hl + row * FOUT + tx * 4) = *(uint2*)lo;

        // fused s/t: partial dot over this thread's 4 cols, reduce over tx group
        float sp = acc[i][0] * as[0] + acc[i][1] * as[1] + acc[i][2] * as[2] + acc[i][3] * as[3];
        float tp = acc[i][0] * ad[0] + acc[i][1] * ad[1] + acc[i][2] * ad[2] + acc[i][3] * ad[3];
#pragma unroll
        for (int o = 8; o; o >>= 1) {
            sp += __shfl_xor_sync(0xffffffffu, sp, o);
            tp += __shfl_xor_sync(0xffffffffu, tp, o);
        }
        if (tx == 0) { g_s[row] = sp; g_t[row] = tp; }
    }
}

// ---------------------------------------------------------------------------
// Kernel B: fused masked-softmax + tensor-core att@h (att fp16, h fp16 hi/lo)
// Block = (32-row tile, batch). 256 threads = 8 warps.
// ---------------------------------------------------------------------------
#define ATT_S 520   // fp16 stride for att rows (512 + 8 pad)
#define HS_S  72    // fp16 stride for h chunk rows (64 + 8 pad)

__global__ void __launch_bounds__(256) attn_kernel(
    const int* __restrict__ adj, float* __restrict__ out)
{
    extern __shared__ char smraw[];
    float* t_sh = (float*)smraw;                     // 512 f32
    float* inv  = t_sh + 512;                        // 32 f32
    float* wmax = inv + 32;                          // 8 f32
    __half* attF = (__half*)(wmax + 8);              // 32 x 520
    __half* hsHi = attF + 32 * ATT_S;                // 64 x 72
    __half* hsLo = hsHi + 64 * HS_S;                 // 64 x 72

    const int b    = blockIdx.y;
    const int r0   = blockIdx.x * 32;
    const int tid  = threadIdx.x;
    const int warp = tid >> 5;
    const int lane = tid & 31;

    float t0 = g_t[b * N_ + tid];
    float t1 = g_t[b * N_ + tid + 256];
    t_sh[tid]       = t0;
    t_sh[tid + 256] = t1;

    // block max of t (for loose-but-exact softmax max via monotonicity of leaky)
    float m2 = fmaxf(t0, t1);
#pragma unroll
    for (int o = 16; o; o >>= 1) m2 = fmaxf(m2, __shfl_xor_sync(0xffffffffu, m2, o));
    if (lane == 0) wmax[warp] = m2;
    __syncthreads();
    float maxT = fmaxf(fmaxf(fmaxf(wmax[0], wmax[1]), fmaxf(wmax[2], wmax[3])),
                       fmaxf(fmaxf(wmax[4], wmax[5]), fmaxf(wmax[6], wmax[7])));

    // ---- Phase 1: masked leaky logits -> unnormalized fp16 softmax weights ----
#pragma unroll
    for (int rr = 0; rr < 4; rr++) {
        int r    = warp * 4 + rr;
        int grow = r0 + r;
        float s  = g_s[b * N_ + grow];
        float mxe = s + maxT;
        float mx  = mxe > 0.f ? mxe : 0.2f * mxe;    // = max_j leaky(s + t_j)
        const int4* arow = (const int4*)(adj + ((size_t)b * N_ + grow) * N_);

        float sum = 0.f;
#pragma unroll
        for (int it = 0; it < 4; it++) {
            int j0 = it * 128 + lane * 4;
            int4 av = arow[it * 32 + lane];
            float w[4];
#pragma unroll
            for (int c = 0; c < 4; c++) {
                float e = s + t_sh[j0 + c];
                e = e > 0.f ? e : 0.2f * e;
                float wv = __expf(e - mx);
                int m = (&av.x)[c];
                w[c] = m > 0 ? wv : 0.f;
                sum += w[c];
            }
            __half2 p0 = __floats2half2_rn(w[0], w[1]);
            __half2 p1 = __floats2half2_rn(w[2], w[3]);
            uint2 pk = make_uint2(*(uint32_t*)&p0, *(uint32_t*)&p1);
            *(uint2*)(attF + r * ATT_S + j0) = pk;
        }
#pragma unroll
        for (int o = 16; o; o >>= 1) sum += __shfl_xor_sync(0xffffffffu, sum, o);
        if (lane == 0) inv[r] = 1.0f / sum;
    }
    __syncthreads();

    // ---- Phase 2: C[32,64] = att @ h[b]  via mma.m16n8k16.f16 (2-term h split) ----
    const int mtile = warp >> 2;          // 0..1 : which m16 tile
    const int ntg0  = (warp & 3) * 2;     // n8 tile pair base
    const int lrow16 = lane & 15;

    uint32_t aAddr  = smem_u32(attF + (mtile * 16 + lrow16) * ATT_S + (lane >> 4) * 8);
    uint32_t bAddrH = smem_u32(hsHi + lrow16 * HS_S + (ntg0 + (lane >> 4)) * 8);
    uint32_t bAddrL = smem_u32(hsLo + lrow16 * HS_S + (ntg0 + (lane >> 4)) * 8);

    float acc0[4] = {0.f, 0.f, 0.f, 0.f};
    float acc1[4] = {0.f, 0.f, 0.f, 0.f};

    const __half* hbHi = g_hh + (size_t)b * N_ * FOUT;
    const __half* hbLo = g_hl + (size_t)b * N_ * FOUT;

    for (int c = 0; c < 8; c++) {
        const int k0 = c * 64;
        // load h chunk [64 k-rows][64 f] hi+lo into smem (uint4 = 8 fp16)
#pragma unroll
        for (int rep = 0; rep < 2; rep++) {
            int u   = rep * 256 + tid;
            int row = u >> 3;
            int off = (u & 7) * 8;
            *(uint4*)(hsHi + row * HS_S + off) = *(const uint4*)(hbHi + (size_t)(k0 + row) * FOUT + off);
            *(uint4*)(hsLo + row * HS_S + off) = *(const uint4*)(hbLo + (size_t)(k0 + row) * FOUT + off);
        }
        __syncthreads();

#pragma unroll
        for (int ks = 0; ks < 4; ks++) {
            const uint32_t aOff = (uint32_t)(k0 + ks * 16) * 2;       // bytes along att row
            const uint32_t bOff = (uint32_t)(ks * 16) * HS_S * 2;     // bytes down h rows

            uint32_t a0, a1, a2, a3;
            ldsm_x4(a0, a1, a2, a3, aAddr + aOff);

            uint32_t bh0, bh1, bh2, bh3, bl0, bl1, bl2, bl3;
            ldsm_x4t(bh0, bh1, bh2, bh3, bAddrH + bOff);
            ldsm_x4t(bl0, bl1, bl2, bl3, bAddrL + bOff);

            mma16816(acc0, a0, a1, a2, a3, bh0, bh1);
            mma16816(acc0, a0, a1, a2, a3, bl0, bl1);
            mma16816(acc1, a0, a1, a2, a3, bh2, bh3);
            mma16816(acc1, a0, a1, a2, a3, bl2, bl3);
        }
        __syncthreads();
    }

    // ---- Epilogue: normalize + leaky_relu(0.01) + store ----
    const int gid = lane >> 2;
    const int tg  = lane & 3;
    const int rA  = mtile * 16 + gid;
    const int rB  = rA + 8;
    const float invA = inv[rA];
    const float invB = inv[rB];

#pragma unroll
    for (int nt = 0; nt < 2; nt++) {
        float* acc = nt ? acc1 : acc0;
        int col = (ntg0 + nt) * 8 + tg * 2;
        float v;
        float2 oA, oB;
        v = acc[0] * invA; oA.x = v > 0.f ? v : 0.01f * v;
        v = acc[1] * invA; oA.y = v > 0.f ? v : 0.01f * v;
        v = acc[2] * invB; oB.x = v > 0.f ? v : 0.01f * v;
        v = acc[3] * invB; oB.y = v > 0.f ? v : 0.01f * v;
        *(float2*)(out + ((size_t)b * N_ + r0 + rA) * FOUT + col) = oA;
        *(float2*)(out + ((size_t)b * N_ + r0 + rB) * FOUT + col) = oB;
    }
}

// ---------------------------------------------------------------------------
extern "C" void kernel_launch(void* const* d_in, const int* in_sizes, int n_in,
                              void* d_out, int out_size)
{
    const float* X   = (const float*)d_in[0];
    const int*   adj = (const int*)  d_in[1];
    const float* W   = (const float*)d_in[2];
    const float* a   = (const float*)d_in[3];
    float* out = (float*)d_out;

    size_t smA = (size_t)(64 * 132 + 128 * 64) * sizeof(float);
    cudaFuncSetAttribute(gemm1_kernel, cudaFuncAttributeMaxDynamicSharedMemorySize, (int)smA);
    gemm1_kernel<<<(B_ * N_) / 64, 256, smA>>>(X, W, a);

    size_t smB = (512 + 32 + 8) * sizeof(float)
               + (size_t)(32 * ATT_S + 2 * 64 * HS_S) * sizeof(__half);
    cudaFuncSetAttribute(attn_kernel, cudaFuncAttributeMaxDynamicSharedMemorySize, (int)smB);
    attn_kernel<<<dim3(N_ / 32, B_), 256, smB>>>(adj, out);
}